// round 14
// baseline (speedup 1.0000x reference)
#include <cuda_runtime.h>
#include <cuda_fp16.h>
#include <cstdint>
#include <cstddef>

#define DEV_INLINE __device__ __forceinline__

constexpr int kB = 4, kC = 128, kH = 128, kW = 128;
constexpr int kHW = kH * kW;

// ======================= scratch (floats) =======================
constexpr size_t O_XT   = 0;
constexpr size_t O_OFFB = 16777216;
constexpr size_t O_XH   = 20971520;
constexpr size_t O_H1H  = 25165824;
constexpr size_t O_H2H  = 29360128;
constexpr size_t O_H3H  = 33554432;
constexpr size_t O_W1   = 54525952;
constexpr size_t O_W2   = 54599680;
constexpr size_t O_WD   = 54673408;
constexpr size_t O_WO   = 54747136;
constexpr size_t O_WC   = 54820864;
constexpr size_t O_SC   = 55058432;
constexpr size_t SCRATCH= 55060608;

__device__ float g_buf[SCRATCH];

// ======================= PTX helpers =======================
DEV_INLINE uint32_t smem_to_u32(const void* p) {
    uint32_t a;
    asm("{ .reg .u64 t; cvta.to.shared.u64 t, %1; cvt.u32.u64 %0, t; }" : "=r"(a) : "l"(p));
    return a;
}
DEV_INLINE void cp16(uint32_t d, const void* s, bool ok) {
    asm volatile("cp.async.ca.shared.global [%0], [%1], 16, %2;"
                 :: "r"(d), "l"(s), "r"(ok ? 16 : 0));
}
DEV_INLINE void cp_commit() { asm volatile("cp.async.commit_group;" ::: "memory"); }
DEV_INLINE void cp_wait0()  { asm volatile("cp.async.wait_group 0;" ::: "memory"); }

DEV_INLINE void ldsm4(uint32_t a, uint32_t& r0, uint32_t& r1, uint32_t& r2, uint32_t& r3) {
    asm volatile("ldmatrix.sync.aligned.m8n8.x4.shared.b16 {%0,%1,%2,%3}, [%4];"
                 : "=r"(r0), "=r"(r1), "=r"(r2), "=r"(r3) : "r"(a));
}
DEV_INLINE void mma16816(float* c, const uint32_t* a, const uint32_t* b) {
    asm volatile("mma.sync.aligned.m16n8k16.row.col.f32.f16.f16.f32 "
                 "{%0,%1,%2,%3},{%4,%5,%6,%7},{%8,%9},{%0,%1,%2,%3};"
                 : "+f"(c[0]), "+f"(c[1]), "+f"(c[2]), "+f"(c[3])
                 : "r"(a[0]), "r"(a[1]), "r"(a[2]), "r"(a[3]), "r"(b[0]), "r"(b[1]));
}
DEV_INLINE uint32_t swz(uint32_t o) { return o ^ ((o >> 3) & 0x70); }

// single-pass mma over one staged K-chunk (padded-80 layout, convs)
template <int MT, int KS>
DEV_INLINE void mma_chunk(uint32_t A, uint32_t B,
                          int as, int bs, int pxb, int ocb, int lane, float (*acc)[4]) {
    const int r = lane & 7, sel = lane >> 3;
    const int aro = (pxb + (sel & 1) * 8 + r) * as;
    const int bro = (ocb + (sel >> 1) * 8 + r) * bs;
#pragma unroll
    for (int ks = 0; ks < KS; ks++) {
        const int ac = (ks * 16 + (sel >> 1) * 8) * 2;
        const int bc = (ks * 16 + (sel & 1) * 8) * 2;
        uint32_t ah[MT][4];
#pragma unroll
        for (int mt = 0; mt < MT; mt++)
            ldsm4(A + aro + mt * 16 * as + ac, ah[mt][0], ah[mt][1], ah[mt][2], ah[mt][3]);
        uint32_t bh[8][2];
#pragma unroll
        for (int jp = 0; jp < 4; jp++) {
            ldsm4(B + bro + jp * 16 * bs + bc,
                  bh[2 * jp][0], bh[2 * jp][1], bh[2 * jp + 1][0], bh[2 * jp + 1][1]);
        }
#pragma unroll
        for (int mt = 0; mt < MT; mt++)
#pragma unroll
            for (int nt = 0; nt < 8; nt++)
                mma16816(acc[mt * 8 + nt], ah[mt], bh[nt]);
    }
}

// swizzled-128B-row mma chunk (deform): rows are 128B, SW128 xor layout
template <int KS>
DEV_INLINE void mma_chunk_sw(uint32_t A, uint32_t B,
                             int pxb, int ocb, int lane, float (*acc)[4]) {
    const int r = lane & 7, sel = lane >> 3;
    const int arow = pxb + (sel & 1) * 8 + r;
    const int brow = ocb + (sel >> 1) * 8 + r;
#pragma unroll
    for (int ks = 0; ks < KS; ks++) {
        const int ac = (ks * 16 + (sel >> 1) * 8) * 2;
        const int bc = (ks * 16 + (sel & 1) * 8) * 2;
        uint32_t ah[2][4];
#pragma unroll
        for (int mt = 0; mt < 2; mt++)
            ldsm4(A + swz((arow + mt * 16) * 128 + ac), ah[mt][0], ah[mt][1], ah[mt][2], ah[mt][3]);
        uint32_t bh[8][2];
#pragma unroll
        for (int jp = 0; jp < 4; jp++) {
            ldsm4(B + swz((brow + jp * 16) * 128 + bc),
                  bh[2 * jp][0], bh[2 * jp][1], bh[2 * jp + 1][0], bh[2 * jp + 1][1]);
        }
#pragma unroll
        for (int mt = 0; mt < 2; mt++)
#pragma unroll
            for (int nt = 0; nt < 8; nt++)
                mma16816(acc[mt * 8 + nt], ah[mt], bh[nt]);
    }
}

// ======================= prep kernels =======================
__global__ void prep_bn_all_k(const float* __restrict__ rb_bn1, const float* __restrict__ rb_b1,
                              const float* __restrict__ rb_bn2, const float* __restrict__ rb_b2,
                              const float* __restrict__ bn1, const float* __restrict__ dc_b,
                              const float* __restrict__ bn2, const float* __restrict__ off_b,
                              float* __restrict__ scbase) {
    int which = blockIdx.x, c = threadIdx.x;
    if (which == 4) {
        if (c < 64) {
            scbase[8 * kC + c] = 1.f;
            scbase[8 * kC + 64 + c] = (c < 54) ? off_b[c] : 0.f;
        }
        return;
    }
    const float* bnp = (which == 0) ? rb_bn1 : (which == 1) ? rb_bn2 : (which == 2) ? bn1 : bn2;
    const float* bias = (which == 0) ? rb_b1 : (which == 1) ? rb_b2 : (which == 2) ? dc_b : nullptr;
    float g = bnp[c], be = bnp[kC + c], m = bnp[2 * kC + c], va = bnp[3 * kC + c];
    float s = g / sqrtf(va + 1e-5f);
    float t = be - m * s;
    if (bias) t += bias[c] * s;
    scbase[which * 2 * kC + c] = s;
    scbase[which * 2 * kC + kC + c] = t;
}

__global__ void wprep_all_k(const float* __restrict__ rb_w1, const float* __restrict__ rb_w2,
                            const float* __restrict__ off_w, const float* __restrict__ dc_w,
                            const float* __restrict__ cv_w,
                            __half* __restrict__ w1, __half* __restrict__ w2,
                            __half* __restrict__ wo, __half* __restrict__ wd,
                            __half* __restrict__ wc) {
    int idx = blockIdx.x * 256 + threadIdx.x;
    if (idx < 147456) {
        int ci = idx & 127, oc = (idx >> 7) & 127, tap = idx >> 14;
        w1[idx] = __float2half_rn(rb_w1[(oc * kC + ci) * 9 + tap]);
    } else if (idx < 294912) {
        int i = idx - 147456;
        int ci = i & 127, oc = (i >> 7) & 127, tap = i >> 14;
        w2[i] = __float2half_rn(rb_w2[(oc * kC + ci) * 9 + tap]);
    } else if (idx < 368640) {
        int i = idx - 294912;
        int ci = i & 127, oc = (i >> 7) & 63, tap = i >> 13;
        wo[i] = __float2half_rn((oc < 54) ? off_w[(oc * kC + ci) * 9 + tap] : 0.f);
    } else if (idx < 516096) {
        int i = idx - 368640;
        int cg = i & 63, oc = (i >> 6) & 127, dk = i >> 13;
        int d = dk / 9, k = dk % 9;
        wd[i] = __float2half_rn(dc_w[(oc * kC + d * 64 + cg) * 9 + k]);
    } else if (idx < 532480) {
        int i = idx - 516096;
        wc[i] = __float2half_rn(cv_w[i]);
    }
}

__global__ void to_nhwc2_k(const float* __restrict__ in, float* __restrict__ outf,
                           __half* __restrict__ oh) {
    __shared__ float t[32][33];
    int b = blockIdx.z, c0 = blockIdx.y * 32, p0 = blockIdx.x * 32;
    int tx = threadIdx.x, ty = threadIdx.y;
#pragma unroll
    for (int k = 0; k < 32; k += 8)
        t[ty + k][tx] = in[(size_t)(b * kC + c0 + ty + k) * kHW + p0 + tx];
    __syncthreads();
#pragma unroll
    for (int k = 0; k < 32; k += 8) {
        float v = t[tx][ty + k];
        size_t o = (size_t)(b * kHW + p0 + ty + k) * kC + c0 + tx;
        outf[o] = v;
        oh[o] = __float2half_rn(v);
    }
}

// ======================= conv kernel (row-reuse implicit GEMM, fp16 1-pass) =======================
template <int NT, int EPI, int TAPS>
__global__ void __launch_bounds__(256, 2)
mma_conv_k(const __half* __restrict__ Ah, const __half* __restrict__ W,
           const float* __restrict__ scale, const float* __restrict__ shift,
           const float* __restrict__ resf, float* __restrict__ outf,
           __half* __restrict__ outh) {
    constexpr int MT   = NT / 64;
    constexpr int HALO = (TAPS == 9) ? 1 : 0;
    constexpr int NTX  = (TAPS == 9) ? 3 : 1;
    constexpr int NTY  = NTX;
    constexpr int PXS  = 128 + 2 * HALO;
    constexpr int PXSP = (TAPS == 9) ? 136 : 128;
    constexpr int ABUF = PXSP * 80;
    constexpr int BPT  = NT * 80;
    constexpr int BPB  = NTX * BPT;
    constexpr int NCH  = NTY * 4;

    extern __shared__ char sm[];
    const uint32_t smA = smem_to_u32(sm);
    const uint32_t smB = smA + 2 * ABUF;

    const int h = blockIdx.x, b = blockIdx.y;
    const int tid = threadIdx.x, wid = tid >> 5, lane = tid & 31;
    const int wm = (NT == 128) ? (wid & 3) : wid;
    const int wn = (NT == 128) ? (wid >> 2) : 0;
    const int pxb = wm * MT * 16;
    const int ocb = wn * 64;

    float acc[MT * 8][4];
#pragma unroll
    for (int i = 0; i < MT * 8; i++)
#pragma unroll
        for (int j = 0; j < 4; j++) acc[i][j] = 0.f;

    auto stage = [&](int cc, int s) {
        const int ty = cc >> 2, cq = cc & 3, c0 = cq * 32;
        const int row = h + ty - HALO;
        const bool rok = (row >= 0) && (row < kH);
        constexpr int ATOT = PXS * 4;
#pragma unroll
        for (int it = 0; it < (ATOT + 255) / 256; it++) {
            int i = it * 256 + tid;
            if ((ATOT & 255) && i >= ATOT) break;
            int slot = i >> 2, j = i & 3;
            int inpx = slot - HALO;
            bool ok = rok && ((unsigned)inpx < 128u);
            const __half* src = Ah +
                ((size_t)(b * kHW + (ok ? row * kW + inpx : 0)) * kC + c0 + j * 8);
            cp16(smA + s * ABUF + slot * 80 + j * 16, src, ok);
        }
#pragma unroll
        for (int it = 0; it < NTX * NT / 64; it++) {
            int i = it * 256 + tid;
            int txn = i / (NT * 4), rem = i % (NT * 4), oc = rem >> 2, j = rem & 3;
            int tap = ty * 3 + txn;
            const __half* src = W + ((size_t)(tap * NT + oc)) * kC + c0 + j * 8;
            cp16(smB + s * BPB + txn * BPT + oc * 80 + j * 16, src, true);
        }
    };

    stage(0, 0); cp_commit();
#pragma unroll 1
    for (int cc = 0; cc < NCH; cc++) {
        const int s = cc & 1;
        cp_wait0();
        __syncthreads();
        if (cc + 1 < NCH) { stage(cc + 1, s ^ 1); cp_commit(); }
#pragma unroll
        for (int tx = 0; tx < NTX; tx++) {
            mma_chunk<MT, 2>(smA + s * ABUF + tx * 80,
                             smB + s * BPB + tx * BPT,
                             80, 80, pxb, ocb, lane, acc);
        }
    }

    // ---- epilogue ----
    const int r4 = lane >> 2, cp2 = (lane & 3) * 2;
    const size_t rowbase = (size_t)(b * kHW + h * kW);
#pragma unroll
    for (int mt = 0; mt < MT; mt++)
#pragma unroll
        for (int nt = 0; nt < 8; nt++) {
            const int oc = ocb + nt * 8 + cp2;
            const float s0 = scale[oc], s1 = scale[oc + 1];
            const float sh0 = shift[oc], sh1 = shift[oc + 1];
#pragma unroll
            for (int hh = 0; hh < 2; hh++) {
                const int px = pxb + mt * 16 + r4 + hh * 8;
                float v0 = acc[mt * 8 + nt][hh * 2 + 0] * s0 + sh0;
                float v1 = acc[mt * 8 + nt][hh * 2 + 1] * s1 + sh1;
                const size_t pix = rowbase + px;
                if (EPI == 1) {
                    float2 rr = *(const float2*)(resf + pix * kC + oc);
                    v0 += rr.x; v1 += rr.y;
                }
                if (EPI == 0 || EPI == 1) { v0 = fmaxf(v0, 0.f); v1 = fmaxf(v1, 0.f); }
                if (EPI == 4) {
                    v0 = (v0 > 0.f) ? v0 : 0.1f * v0;
                    v1 = (v1 > 0.f) ? v1 : 0.1f * v1;
                    size_t i0 = (size_t)(b * kC + oc) * kHW + h * kW + px;
                    outf[i0] = resf[i0] + v0;
                    outf[i0 + kHW] = resf[i0 + kHW] + v1;
                } else if (EPI == 2) {
                    *(float2*)(outf + pix * 64 + oc) = make_float2(v0, v1);
                } else {
                    *(__half2*)(outh + pix * kC + oc) =
                        __halves2half2(__float2half_rn(v0), __float2half_rn(v1));
                }
            }
        }
}

// ======================= modulated deformable conv (cp.async gather pipeline) =======================
// smem: raw 64K | A 16K (SW128 swizzled 128B rows, single buf) | B 2x16K (swizzled)
// Per dk: raw(dk) landed during mma(dk-1); blend raw->A; issue raw(dk+1)+B(dk+1); mma(dk).
__global__ void __launch_bounds__(256, 2)
mma_deform_k(const __half* __restrict__ h2h, const float* __restrict__ offb,
             const __half* __restrict__ W,
             const float* __restrict__ scale, const float* __restrict__ shift,
             __half* __restrict__ outh) {
    constexpr int RAWSZ = 65536;
    constexpr int ASZ   = 16384;
    constexpr int BSZ   = 16384;

    extern __shared__ char sm[];
    const uint32_t smRaw = smem_to_u32(sm);
    const uint32_t smA   = smRaw + RAWSZ;
    const uint32_t smB   = smA + ASZ;

    const int h = blockIdx.x, b = blockIdx.y;
    const int tid = threadIdx.x, wid = tid >> 5, lane = tid & 31;
    const int wm = wid & 3, wn = wid >> 2;
    const int pxb = wm * 32, ocb = wn * 64;
    const int spx = tid >> 1, half = tid & 1;

    float acc[16][4];
#pragma unroll
    for (int i = 0; i < 16; i++)
#pragma unroll
        for (int j = 0; j < 4; j++) acc[i][j] = 0.f;

    const float* op = offb + ((size_t)(b * kHW + h * kW + spx)) * 64;
    const __half* h2b = h2h + (size_t)b * kHW * kC;

    // Issue the 16 raw cp.asyncs for dk; returns corner weights (carried to blend).
    auto issue_gather = [&](int dk, float* cw) {
        int d = dk / 9, k = dk % 9;
        float oy = op[d * 18 + 2 * k], ox = op[d * 18 + 2 * k + 1];
        float ml = op[36 + d * 9 + k];
        float m = 1.f / (1.f + __expf(-ml));
        float py = oy + (float)(h + k / 3 - 1);
        float pxx = ox + (float)(spx + k % 3 - 1);
        float y0f = floorf(py), x0f = floorf(pxx);
        float fy = py - y0f, fx = pxx - x0f;
        int y0 = (int)y0f, x0 = (int)x0f;
        cw[0] = (1.f - fy) * (1.f - fx) * m;
        cw[1] = (1.f - fy) * fx * m;
        cw[2] = fy * (1.f - fx) * m;
        cw[3] = fy * fx * m;
        int cy[4] = {y0, y0, y0 + 1, y0 + 1};
        int cx[4] = {x0, x0 + 1, x0, x0 + 1};
        const int chof = d * 64 + half * 32;
#pragma unroll
        for (int cn = 0; cn < 4; cn++) {
            int y = cy[cn], x = cx[cn];
            bool ok = (y >= 0) && (y < kH) && (x >= 0) && (x < kW);
            const __half* src = h2b + ((size_t)((ok ? y * kW + x : 0)) * kC + chof);
#pragma unroll
            for (int q = 0; q < 4; q++)
                cp16(smRaw + ((cn * 4 + q) * 256 + tid) * 16, src + q * 8, ok);
        }
    };

    // Blend raw(dk) -> A tile (swizzled 128B rows).
    auto blend = [&](const float* cw) {
        float rr[32];
#pragma unroll
        for (int j = 0; j < 32; j++) rr[j] = 0.f;
#pragma unroll
        for (int cn = 0; cn < 4; cn++) {
            float wg = cw[cn];
#pragma unroll
            for (int q = 0; q < 4; q++) {
                uint4 u = *(const uint4*)(sm + ((cn * 4 + q) * 256 + tid) * 16);
                const __half2* hp = (const __half2*)&u;
#pragma unroll
                for (int t = 0; t < 4; t++) {
                    float2 f = __half22float2(hp[t]);
                    rr[q * 8 + t * 2 + 0] += wg * f.x;
                    rr[q * 8 + t * 2 + 1] += wg * f.y;
                }
            }
        }
        __align__(16) __half hb[32];
#pragma unroll
        for (int j = 0; j < 32; j++) hb[j] = __float2half_rn(rr[j]);
#pragma unroll
        for (int q2 = 0; q2 < 4; q2++) {
            uint32_t o = (uint32_t)(spx * 128 + half * 64 + q2 * 16);
            *(uint4*)(sm + RAWSZ + swz(o)) = ((const uint4*)hb)[q2];
        }
    };

    auto stageB = [&](int dk, int s) {
#pragma unroll
        for (int it = 0; it < 4; it++) {
            int i = it * 256 + tid;
            int oc = i >> 3, j = i & 7;
            const __half* src = W + ((size_t)(dk * 128 + oc)) * 64 + j * 8;
            cp16(smB + s * BSZ + swz((uint32_t)(oc * 128 + j * 16)), src, true);
        }
    };

    float cw[4];
    issue_gather(0, cw);
    stageB(0, 0);
    cp_commit();

#pragma unroll 1
    for (int dk = 0; dk < 18; dk++) {
        const int s = dk & 1;
        cp_wait0();
        __syncthreads();                 // raw(dk)+B(dk) visible; mma(dk-1) done -> A safe
        blend(cw);                       // raw(dk) -> A
        if (dk + 1 < 18) {
            issue_gather(dk + 1, cw);    // raw cp.asyncs fly during mma(dk)
            stageB(dk + 1, s ^ 1);
            cp_commit();
        }
        __syncthreads();                 // A visible
        mma_chunk_sw<4>(smA, smB + s * BSZ, pxb, ocb, lane, acc);
    }

    // ---- epilogue: leaky(bn) -> fp16 NHWC ----
    const int r4 = lane >> 2, cp2 = (lane & 3) * 2;
    const size_t rowbase = (size_t)(b * kHW + h * kW);
#pragma unroll
    for (int mt = 0; mt < 2; mt++)
#pragma unroll
        for (int nt = 0; nt < 8; nt++) {
            const int oc = ocb + nt * 8 + cp2;
            const float s0 = scale[oc], s1 = scale[oc + 1];
            const float sh0 = shift[oc], sh1 = shift[oc + 1];
#pragma unroll
            for (int hh = 0; hh < 2; hh++) {
                const int px = pxb + mt * 16 + r4 + hh * 8;
                float v0 = acc[mt * 8 + nt][hh * 2 + 0] * s0 + sh0;
                float v1 = acc[mt * 8 + nt][hh * 2 + 1] * s1 + sh1;
                v0 = (v0 > 0.f) ? v0 : 0.1f * v0;
                v1 = (v1 > 0.f) ? v1 : 0.1f * v1;
                const size_t pix = rowbase + px;
                *(__half2*)(outh + pix * kC + oc) =
                    __halves2half2(__float2half_rn(v0), __float2half_rn(v1));
            }
        }
}

// ======================= launch =======================
extern "C" void kernel_launch(void* const* d_in, const int* in_sizes, int n_in,
                              void* d_out, int out_size) {
    (void)in_sizes; (void)n_in; (void)out_size;
    const float* x      = (const float*)d_in[0];
    const float* rb_w1  = (const float*)d_in[1];
    const float* rb_b1  = (const float*)d_in[2];
    const float* rb_bn1 = (const float*)d_in[3];
    const float* rb_w2  = (const float*)d_in[4];
    const float* rb_b2  = (const float*)d_in[5];
    const float* rb_bn2 = (const float*)d_in[6];
    const float* off_w  = (const float*)d_in[7];
    const float* off_b  = (const float*)d_in[8];
    const float* dc_w   = (const float*)d_in[9];
    const float* dc_b   = (const float*)d_in[10];
    const float* bn1    = (const float*)d_in[11];
    const float* cv2_w  = (const float*)d_in[12];
    const float* bn2    = (const float*)d_in[13];
    float* out = (float*)d_out;

    float* base = nullptr;
    cudaGetSymbolAddress((void**)&base, g_buf);
    float* xt    = base + O_XT;
    float* offb_ = base + O_OFFB;
    __half* xh  = (__half*)(base + O_XH);
    __half* h1h = (__half*)(base + O_H1H);
    __half* h2h = (__half*)(base + O_H2H);
    __half* h3h = (__half*)(base + O_H3H);
    __half* w1 = (__half*)(base + O_W1);
    __half* w2 = (__half*)(base + O_W2);
    __half* wd = (__half*)(base + O_WD);
    __half* wo = (__half*)(base + O_WO);
    __half* wc = (__half*)(base + O_WC);
    float* scb = base + O_SC;
    float* s1 = scb + 0 * kC;   float* t1 = scb + 1 * kC;
    float* s2 = scb + 2 * kC;   float* t2 = scb + 3 * kC;
    float* s3 = scb + 4 * kC;   float* t3 = scb + 5 * kC;
    float* s4 = scb + 6 * kC;   float* t4 = scb + 7 * kC;
    float* soff = scb + 8 * kC; float* toff = soff + 64;

    wprep_all_k<<<(532480 + 255) / 256, 256>>>(rb_w1, rb_w2, off_w, dc_w, cv2_w,
                                               w1, w2, wo, wd, wc);
    prep_bn_all_k<<<5, kC>>>(rb_bn1, rb_b1, rb_bn2, rb_b2, bn1, dc_b, bn2, off_b, scb);
    to_nhwc2_k<<<dim3(kHW / 32, kC / 32, kB), dim3(32, 8)>>>(x, xt, xh);

    constexpr int SM1  = 2 * (136 * 80) + 2 * (3 * 128 * 80);  // 83200
    constexpr int SMO  = 2 * (136 * 80) + 2 * (3 * 64 * 80);   // 52480
    constexpr int SMC  = 2 * (128 * 80) + 2 * (1 * 128 * 80);  // 40960
    constexpr int SMDEF = 65536 + 16384 + 2 * 16384;           // 114688
    dim3 grid(kH, kB);

    cudaFuncSetAttribute(mma_conv_k<128, 0, 9>, cudaFuncAttributeMaxDynamicSharedMemorySize, SM1);
    cudaFuncSetAttribute(mma_conv_k<128, 1, 9>, cudaFuncAttributeMaxDynamicSharedMemorySize, SM1);
    cudaFuncSetAttribute(mma_conv_k<64, 2, 9>,  cudaFuncAttributeMaxDynamicSharedMemorySize, SMO);
    cudaFuncSetAttribute(mma_conv_k<128, 4, 1>, cudaFuncAttributeMaxDynamicSharedMemorySize, SMC);
    cudaFuncSetAttribute(mma_deform_k,          cudaFuncAttributeMaxDynamicSharedMemorySize, SMDEF);

    mma_conv_k<128, 0, 9><<<grid, 256, SM1>>>(xh, w1, s1, t1,
                                              nullptr, nullptr, h1h);
    mma_conv_k<128, 1, 9><<<grid, 256, SM1>>>(h1h, w2, s2, t2,
                                              xt, nullptr, h2h);
    mma_conv_k<64, 2, 9><<<grid, 256, SMO>>>(h2h, wo, soff, toff,
                                             nullptr, offb_, nullptr);
    mma_deform_k<<<grid, 256, SMDEF>>>(h2h, offb_, wd, s3, t3, h3h);
    mma_conv_k<128, 4, 1><<<grid, 256, SMC>>>(h3h, wc, s4, t4,
                                              x, out, nullptr);
}

// round 15
// speedup vs baseline: 1.1266x; 1.1266x over previous
#include <cuda_runtime.h>
#include <cuda_fp16.h>
#include <cstdint>
#include <cstddef>

#define DEV_INLINE __device__ __forceinline__

constexpr int kB = 4, kC = 128, kH = 128, kW = 128;
constexpr int kHW = kH * kW;

// ======================= scratch (floats) =======================
constexpr size_t O_XT   = 0;
constexpr size_t O_OFFB = 16777216;
constexpr size_t O_XH   = 20971520;
constexpr size_t O_H1H  = 25165824;
constexpr size_t O_H2H  = 29360128;
constexpr size_t O_H3H  = 33554432;
constexpr size_t O_W1   = 54525952;
constexpr size_t O_W2   = 54599680;
constexpr size_t O_WD   = 54673408;
constexpr size_t O_WO   = 54747136;
constexpr size_t O_WC   = 54820864;
constexpr size_t O_SC   = 55058432;
constexpr size_t SCRATCH= 55060608;

__device__ float g_buf[SCRATCH];

// ======================= PTX helpers =======================
DEV_INLINE uint32_t smem_to_u32(const void* p) {
    uint32_t a;
    asm("{ .reg .u64 t; cvta.to.shared.u64 t, %1; cvt.u32.u64 %0, t; }" : "=r"(a) : "l"(p));
    return a;
}
DEV_INLINE void cp16(uint32_t d, const void* s, bool ok) {
    asm volatile("cp.async.ca.shared.global [%0], [%1], 16, %2;"
                 :: "r"(d), "l"(s), "r"(ok ? 16 : 0));
}
DEV_INLINE void cp_commit() { asm volatile("cp.async.commit_group;" ::: "memory"); }
DEV_INLINE void cp_wait0()  { asm volatile("cp.async.wait_group 0;" ::: "memory"); }
DEV_INLINE void cp_wait1()  { asm volatile("cp.async.wait_group 1;" ::: "memory"); }

DEV_INLINE void ldsm4(uint32_t a, uint32_t& r0, uint32_t& r1, uint32_t& r2, uint32_t& r3) {
    asm volatile("ldmatrix.sync.aligned.m8n8.x4.shared.b16 {%0,%1,%2,%3}, [%4];"
                 : "=r"(r0), "=r"(r1), "=r"(r2), "=r"(r3) : "r"(a));
}
DEV_INLINE void mma16816(float* c, const uint32_t* a, const uint32_t* b) {
    asm volatile("mma.sync.aligned.m16n8k16.row.col.f32.f16.f16.f32 "
                 "{%0,%1,%2,%3},{%4,%5,%6,%7},{%8,%9},{%0,%1,%2,%3};"
                 : "+f"(c[0]), "+f"(c[1]), "+f"(c[2]), "+f"(c[3])
                 : "r"(a[0]), "r"(a[1]), "r"(a[2]), "r"(a[3]), "r"(b[0]), "r"(b[1]));
}

// single-pass mma over one staged K-chunk: MT m-tiles x 8 n-tiles, KS k16 steps.
template <int MT, int KS>
DEV_INLINE void mma_chunk(uint32_t A, uint32_t B,
                          int as, int bs, int pxb, int ocb, int lane, float (*acc)[4]) {
    const int r = lane & 7, sel = lane >> 3;
    const int aro = (pxb + (sel & 1) * 8 + r) * as;
    const int bro = (ocb + (sel >> 1) * 8 + r) * bs;
#pragma unroll
    for (int ks = 0; ks < KS; ks++) {
        const int ac = (ks * 16 + (sel >> 1) * 8) * 2;
        const int bc = (ks * 16 + (sel & 1) * 8) * 2;
        uint32_t ah[MT][4];
#pragma unroll
        for (int mt = 0; mt < MT; mt++)
            ldsm4(A + aro + mt * 16 * as + ac, ah[mt][0], ah[mt][1], ah[mt][2], ah[mt][3]);
        uint32_t bh[8][2];
#pragma unroll
        for (int jp = 0; jp < 4; jp++) {
            ldsm4(B + bro + jp * 16 * bs + bc,
                  bh[2 * jp][0], bh[2 * jp][1], bh[2 * jp + 1][0], bh[2 * jp + 1][1]);
        }
#pragma unroll
        for (int mt = 0; mt < MT; mt++)
#pragma unroll
            for (int nt = 0; nt < 8; nt++)
                mma16816(acc[mt * 8 + nt], ah[mt], bh[nt]);
    }
}

// ======================= prep kernels =======================
__global__ void prep_bn_all_k(const float* __restrict__ rb_bn1, const float* __restrict__ rb_b1,
                              const float* __restrict__ rb_bn2, const float* __restrict__ rb_b2,
                              const float* __restrict__ bn1, const float* __restrict__ dc_b,
                              const float* __restrict__ bn2, const float* __restrict__ off_b,
                              float* __restrict__ scbase) {
    int which = blockIdx.x, c = threadIdx.x;
    if (which == 4) {
        if (c < 64) {
            scbase[8 * kC + c] = 1.f;
            scbase[8 * kC + 64 + c] = (c < 54) ? off_b[c] : 0.f;
        }
        return;
    }
    const float* bnp = (which == 0) ? rb_bn1 : (which == 1) ? rb_bn2 : (which == 2) ? bn1 : bn2;
    const float* bias = (which == 0) ? rb_b1 : (which == 1) ? rb_b2 : (which == 2) ? dc_b : nullptr;
    float g = bnp[c], be = bnp[kC + c], m = bnp[2 * kC + c], va = bnp[3 * kC + c];
    float s = g / sqrtf(va + 1e-5f);
    float t = be - m * s;
    if (bias) t += bias[c] * s;
    scbase[which * 2 * kC + c] = s;
    scbase[which * 2 * kC + kC + c] = t;
}

__global__ void wprep_all_k(const float* __restrict__ rb_w1, const float* __restrict__ rb_w2,
                            const float* __restrict__ off_w, const float* __restrict__ dc_w,
                            const float* __restrict__ cv_w,
                            __half* __restrict__ w1, __half* __restrict__ w2,
                            __half* __restrict__ wo, __half* __restrict__ wd,
                            __half* __restrict__ wc) {
    int idx = blockIdx.x * 256 + threadIdx.x;
    if (idx < 147456) {
        int ci = idx & 127, oc = (idx >> 7) & 127, tap = idx >> 14;
        w1[idx] = __float2half_rn(rb_w1[(oc * kC + ci) * 9 + tap]);
    } else if (idx < 294912) {
        int i = idx - 147456;
        int ci = i & 127, oc = (i >> 7) & 127, tap = i >> 14;
        w2[i] = __float2half_rn(rb_w2[(oc * kC + ci) * 9 + tap]);
    } else if (idx < 368640) {
        int i = idx - 294912;
        int ci = i & 127, oc = (i >> 7) & 63, tap = i >> 13;
        wo[i] = __float2half_rn((oc < 54) ? off_w[(oc * kC + ci) * 9 + tap] : 0.f);
    } else if (idx < 516096) {
        int i = idx - 368640;
        int cg = i & 63, oc = (i >> 6) & 127, dk = i >> 13;
        int d = dk / 9, k = dk % 9;
        wd[i] = __float2half_rn(dc_w[(oc * kC + d * 64 + cg) * 9 + k]);
    } else if (idx < 532480) {
        int i = idx - 516096;
        wc[i] = __float2half_rn(cv_w[i]);
    }
}

__global__ void to_nhwc2_k(const float* __restrict__ in, float* __restrict__ outf,
                           __half* __restrict__ oh) {
    __shared__ float t[32][33];
    int b = blockIdx.z, c0 = blockIdx.y * 32, p0 = blockIdx.x * 32;
    int tx = threadIdx.x, ty = threadIdx.y;
#pragma unroll
    for (int k = 0; k < 32; k += 8)
        t[ty + k][tx] = in[(size_t)(b * kC + c0 + ty + k) * kHW + p0 + tx];
    __syncthreads();
#pragma unroll
    for (int k = 0; k < 32; k += 8) {
        float v = t[tx][ty + k];
        size_t o = (size_t)(b * kHW + p0 + ty + k) * kC + c0 + tx;
        outf[o] = v;
        oh[o] = __float2half_rn(v);
    }
}

// ======================= conv kernel (row-reuse implicit GEMM, fp16 1-pass) =======================
template <int NT, int EPI, int TAPS>
__global__ void __launch_bounds__(256, 2)
mma_conv_k(const __half* __restrict__ Ah, const __half* __restrict__ W,
           const float* __restrict__ scale, const float* __restrict__ shift,
           const float* __restrict__ resf, float* __restrict__ outf,
           __half* __restrict__ outh) {
    constexpr int MT   = NT / 64;
    constexpr int HALO = (TAPS == 9) ? 1 : 0;
    constexpr int NTX  = (TAPS == 9) ? 3 : 1;
    constexpr int NTY  = NTX;
    constexpr int PXS  = 128 + 2 * HALO;
    constexpr int PXSP = (TAPS == 9) ? 136 : 128;
    constexpr int ABUF = PXSP * 80;
    constexpr int BPT  = NT * 80;
    constexpr int BPB  = NTX * BPT;
    constexpr int NCH  = NTY * 4;

    extern __shared__ char sm[];
    const uint32_t smA = smem_to_u32(sm);
    const uint32_t smB = smA + 2 * ABUF;

    const int h = blockIdx.x, b = blockIdx.y;
    const int tid = threadIdx.x, wid = tid >> 5, lane = tid & 31;
    const int wm = (NT == 128) ? (wid & 3) : wid;
    const int wn = (NT == 128) ? (wid >> 2) : 0;
    const int pxb = wm * MT * 16;
    const int ocb = wn * 64;

    float acc[MT * 8][4];
#pragma unroll
    for (int i = 0; i < MT * 8; i++)
#pragma unroll
        for (int j = 0; j < 4; j++) acc[i][j] = 0.f;

    auto stage = [&](int cc, int s) {
        const int ty = cc >> 2, cq = cc & 3, c0 = cq * 32;
        const int row = h + ty - HALO;
        const bool rok = (row >= 0) && (row < kH);
        constexpr int ATOT = PXS * 4;
#pragma unroll
        for (int it = 0; it < (ATOT + 255) / 256; it++) {
            int i = it * 256 + tid;
            if ((ATOT & 255) && i >= ATOT) break;
            int slot = i >> 2, j = i & 3;
            int inpx = slot - HALO;
            bool ok = rok && ((unsigned)inpx < 128u);
            const __half* src = Ah +
                ((size_t)(b * kHW + (ok ? row * kW + inpx : 0)) * kC + c0 + j * 8);
            cp16(smA + s * ABUF + slot * 80 + j * 16, src, ok);
        }
#pragma unroll
        for (int it = 0; it < NTX * NT / 64; it++) {
            int i = it * 256 + tid;
            int txn = i / (NT * 4), rem = i % (NT * 4), oc = rem >> 2, j = rem & 3;
            int tap = ty * 3 + txn;
            const __half* src = W + ((size_t)(tap * NT + oc)) * kC + c0 + j * 8;
            cp16(smB + s * BPB + txn * BPT + oc * 80 + j * 16, src, true);
        }
    };

    stage(0, 0); cp_commit();
#pragma unroll 1
    for (int cc = 0; cc < NCH; cc++) {
        const int s = cc & 1;
        cp_wait0();
        __syncthreads();
        if (cc + 1 < NCH) { stage(cc + 1, s ^ 1); cp_commit(); }
#pragma unroll
        for (int tx = 0; tx < NTX; tx++) {
            mma_chunk<MT, 2>(smA + s * ABUF + tx * 80,
                             smB + s * BPB + tx * BPT,
                             80, 80, pxb, ocb, lane, acc);
        }
    }

    // ---- epilogue ----
    const int r4 = lane >> 2, cp2 = (lane & 3) * 2;
    const size_t rowbase = (size_t)(b * kHW + h * kW);
#pragma unroll
    for (int mt = 0; mt < MT; mt++)
#pragma unroll
        for (int nt = 0; nt < 8; nt++) {
            const int oc = ocb + nt * 8 + cp2;
            const float s0 = scale[oc], s1 = scale[oc + 1];
            const float sh0 = shift[oc], sh1 = shift[oc + 1];
#pragma unroll
            for (int hh = 0; hh < 2; hh++) {
                const int px = pxb + mt * 16 + r4 + hh * 8;
                float v0 = acc[mt * 8 + nt][hh * 2 + 0] * s0 + sh0;
                float v1 = acc[mt * 8 + nt][hh * 2 + 1] * s1 + sh1;
                const size_t pix = rowbase + px;
                if (EPI == 1) {
                    float2 rr = *(const float2*)(resf + pix * kC + oc);
                    v0 += rr.x; v1 += rr.y;
                }
                if (EPI == 0 || EPI == 1) { v0 = fmaxf(v0, 0.f); v1 = fmaxf(v1, 0.f); }
                if (EPI == 4) {
                    v0 = (v0 > 0.f) ? v0 : 0.1f * v0;
                    v1 = (v1 > 0.f) ? v1 : 0.1f * v1;
                    size_t i0 = (size_t)(b * kC + oc) * kHW + h * kW + px;
                    outf[i0] = resf[i0] + v0;
                    outf[i0 + kHW] = resf[i0 + kHW] + v1;
                } else if (EPI == 2) {
                    *(float2*)(outf + pix * 64 + oc) = make_float2(v0, v1);
                } else {
                    *(__half2*)(outh + pix * kC + oc) =
                        __halves2half2(__float2half_rn(v0), __float2half_rn(v1));
                }
            }
        }
}

// ======================= modulated deformable conv (R13 structure, branchless gather) =======================
__global__ void __launch_bounds__(256, 2)
mma_deform_k(const __half* __restrict__ h2h, const float* __restrict__ offb,
             const __half* __restrict__ W,
             const float* __restrict__ scale, const float* __restrict__ shift,
             __half* __restrict__ outh) {
    constexpr int ABUF = 128 * 144;
    constexpr int BSZ  = 128 * 144;

    extern __shared__ char sm[];
    const uint32_t smA = smem_to_u32(sm);
    const uint32_t smB = smA + 2 * ABUF;

    const int h = blockIdx.x, b = blockIdx.y;
    const int tid = threadIdx.x, wid = tid >> 5, lane = tid & 31;
    const int wm = wid & 3, wn = wid >> 2;
    const int pxb = wm * 32, ocb = wn * 64;
    const int spx = tid >> 1, half = tid & 1;

    float acc[16][4];
#pragma unroll
    for (int i = 0; i < 16; i++)
#pragma unroll
        for (int j = 0; j < 4; j++) acc[i][j] = 0.f;

    const float* op = offb + ((size_t)(b * kHW + h * kW + spx)) * 64;
    const __half* h2b = h2h + (size_t)b * kHW * kC;

    // Branchless gather: clamped addresses, OOB folded into weights (exact same math).
    auto gath = [&](int dk, __half* hb) {
        int d = dk / 9, k = dk % 9;
        float oy = op[d * 18 + 2 * k], ox = op[d * 18 + 2 * k + 1];
        float ml = op[36 + d * 9 + k];
        float m = 1.f / (1.f + __expf(-ml));
        float py = oy + (float)(h + k / 3 - 1);
        float pxx = ox + (float)(spx + k % 3 - 1);
        float y0f = floorf(py), x0f = floorf(pxx);
        float fy = py - y0f, fx = pxx - x0f;
        int y0 = (int)y0f, x0 = (int)x0f;
        float wy[2] = {1.f - fy, fy};
        float wx[2] = {1.f - fx, fx};
        const __half* bp = h2b + d * 64 + half * 32;

        const uint4* pc[4];
        float wg[4];
#pragma unroll
        for (int cn = 0; cn < 4; cn++) {
            int y = y0 + (cn >> 1), x = x0 + (cn & 1);
            bool ok = (y >= 0) && (y < kH) && (x >= 0) && (x < kW);
            wg[cn] = wy[cn >> 1] * wx[cn & 1] * m * (ok ? 1.f : 0.f);
            int yc = min(max(y, 0), kH - 1), xc = min(max(x, 0), kW - 1);
            pc[cn] = (const uint4*)(bp + (size_t)(yc * kW + xc) * kC);
        }
        float rr[32];
#pragma unroll
        for (int j = 0; j < 32; j++) rr[j] = 0.f;
#pragma unroll
        for (int cn = 0; cn < 4; cn++) {
            uint4 u0 = pc[cn][0], u1 = pc[cn][1], u2 = pc[cn][2], u3 = pc[cn][3];
            float w = wg[cn];
            const __half2* h0 = (const __half2*)&u0;
            const __half2* h1 = (const __half2*)&u1;
            const __half2* h2 = (const __half2*)&u2;
            const __half2* h3 = (const __half2*)&u3;
#pragma unroll
            for (int t = 0; t < 4; t++) {
                float2 f0 = __half22float2(h0[t]);
                float2 f1 = __half22float2(h1[t]);
                float2 f2 = __half22float2(h2[t]);
                float2 f3 = __half22float2(h3[t]);
                rr[t * 2 + 0]      += w * f0.x;  rr[t * 2 + 1]      += w * f0.y;
                rr[8 + t * 2 + 0]  += w * f1.x;  rr[8 + t * 2 + 1]  += w * f1.y;
                rr[16 + t * 2 + 0] += w * f2.x;  rr[16 + t * 2 + 1] += w * f2.y;
                rr[24 + t * 2 + 0] += w * f3.x;  rr[24 + t * 2 + 1] += w * f3.y;
            }
        }
#pragma unroll
        for (int j = 0; j < 32; j++) hb[j] = __float2half_rn(rr[j]);
    };

    auto sts = [&](int s, const __half* hb) {
        uint32_t bofs = spx * 144 + half * 64;
#pragma unroll
        for (int q = 0; q < 4; q++)
            *(uint4*)(sm + (size_t)s * ABUF + bofs + q * 16) = ((const uint4*)hb)[q];
    };

    auto stageB = [&](int dk, int s) {
#pragma unroll
        for (int it = 0; it < 4; it++) {
            int i = it * 256 + tid;
            int oc = i >> 3, j = i & 7;
            const __half* src = W + ((size_t)(dk * 128 + oc)) * 64 + j * 8;
            cp16(smB + s * BSZ + oc * 144 + j * 16, src, true);
        }
    };

    __align__(16) __half hb[32];
    gath(0, hb);
    sts(0, hb);
    stageB(0, 0); cp_commit();

#pragma unroll 1
    for (int dk = 0; dk < 18; dk++) {
        const int s = dk & 1;
        const bool more = (dk + 1 < 18);
        if (more) {
            gath(dk + 1, hb);                // gather for next dk (loads batched, branchless)
            stageB(dk + 1, s ^ 1); cp_commit();
            cp_wait1();                      // B(dk) landed
        } else {
            cp_wait0();
        }
        __syncthreads();                     // mma(dk-1) done everywhere; STS(dk) visible
        if (more) sts(s ^ 1, hb);            // overlaps mma(dk) of other warps
        mma_chunk<2, 4>(smA + s * ABUF, smB + s * BSZ,
                        144, 144, pxb, ocb, lane, acc);
    }

    // ---- epilogue: leaky(bn) -> fp16 NHWC ----
    const int r4 = lane >> 2, cp2 = (lane & 3) * 2;
    const size_t rowbase = (size_t)(b * kHW + h * kW);
#pragma unroll
    for (int mt = 0; mt < 2; mt++)
#pragma unroll
        for (int nt = 0; nt < 8; nt++) {
            const int oc = ocb + nt * 8 + cp2;
            const float s0 = scale[oc], s1 = scale[oc + 1];
            const float sh0 = shift[oc], sh1 = shift[oc + 1];
#pragma unroll
            for (int hh = 0; hh < 2; hh++) {
                const int px = pxb + mt * 16 + r4 + hh * 8;
                float v0 = acc[mt * 8 + nt][hh * 2 + 0] * s0 + sh0;
                float v1 = acc[mt * 8 + nt][hh * 2 + 1] * s1 + sh1;
                v0 = (v0 > 0.f) ? v0 : 0.1f * v0;
                v1 = (v1 > 0.f) ? v1 : 0.1f * v1;
                const size_t pix = rowbase + px;
                *(__half2*)(outh + pix * kC + oc) =
                    __halves2half2(__float2half_rn(v0), __float2half_rn(v1));
            }
        }
}

// ======================= launch =======================
extern "C" void kernel_launch(void* const* d_in, const int* in_sizes, int n_in,
                              void* d_out, int out_size) {
    (void)in_sizes; (void)n_in; (void)out_size;
    const float* x      = (const float*)d_in[0];
    const float* rb_w1  = (const float*)d_in[1];
    const float* rb_b1  = (const float*)d_in[2];
    const float* rb_bn1 = (const float*)d_in[3];
    const float* rb_w2  = (const float*)d_in[4];
    const float* rb_b2  = (const float*)d_in[5];
    const float* rb_bn2 = (const float*)d_in[6];
    const float* off_w  = (const float*)d_in[7];
    const float* off_b  = (const float*)d_in[8];
    const float* dc_w   = (const float*)d_in[9];
    const float* dc_b   = (const float*)d_in[10];
    const float* bn1    = (const float*)d_in[11];
    const float* cv2_w  = (const float*)d_in[12];
    const float* bn2    = (const float*)d_in[13];
    float* out = (float*)d_out;

    float* base = nullptr;
    cudaGetSymbolAddress((void**)&base, g_buf);
    float* xt    = base + O_XT;
    float* offb_ = base + O_OFFB;
    __half* xh  = (__half*)(base + O_XH);
    __half* h1h = (__half*)(base + O_H1H);
    __half* h2h = (__half*)(base + O_H2H);
    __half* h3h = (__half*)(base + O_H3H);
    __half* w1 = (__half*)(base + O_W1);
    __half* w2 = (__half*)(base + O_W2);
    __half* wd = (__half*)(base + O_WD);
    __half* wo = (__half*)(base + O_WO);
    __half* wc = (__half*)(base + O_WC);
    float* scb = base + O_SC;
    float* s1 = scb + 0 * kC;   float* t1 = scb + 1 * kC;
    float* s2 = scb + 2 * kC;   float* t2 = scb + 3 * kC;
    float* s3 = scb + 4 * kC;   float* t3 = scb + 5 * kC;
    float* s4 = scb + 6 * kC;   float* t4 = scb + 7 * kC;
    float* soff = scb + 8 * kC; float* toff = soff + 64;

    wprep_all_k<<<(532480 + 255) / 256, 256>>>(rb_w1, rb_w2, off_w, dc_w, cv2_w,
                                               w1, w2, wo, wd, wc);
    prep_bn_all_k<<<5, kC>>>(rb_bn1, rb_b1, rb_bn2, rb_b2, bn1, dc_b, bn2, off_b, scb);
    to_nhwc2_k<<<dim3(kHW / 32, kC / 32, kB), dim3(32, 8)>>>(x, xt, xh);

    constexpr int SM1  = 2 * (136 * 80) + 2 * (3 * 128 * 80);  // 83200
    constexpr int SMO  = 2 * (136 * 80) + 2 * (3 * 64 * 80);   // 52480
    constexpr int SMC  = 2 * (128 * 80) + 2 * (1 * 128 * 80);  // 40960
    constexpr int SMDEF = 2 * (128 * 144) + 2 * (128 * 144);   // 73728
    dim3 grid(kH, kB);

    cudaFuncSetAttribute(mma_conv_k<128, 0, 9>, cudaFuncAttributeMaxDynamicSharedMemorySize, SM1);
    cudaFuncSetAttribute(mma_conv_k<128, 1, 9>, cudaFuncAttributeMaxDynamicSharedMemorySize, SM1);
    cudaFuncSetAttribute(mma_conv_k<64, 2, 9>,  cudaFuncAttributeMaxDynamicSharedMemorySize, SMO);
    cudaFuncSetAttribute(mma_conv_k<128, 4, 1>, cudaFuncAttributeMaxDynamicSharedMemorySize, SMC);
    cudaFuncSetAttribute(mma_deform_k,          cudaFuncAttributeMaxDynamicSharedMemorySize, SMDEF);

    mma_conv_k<128, 0, 9><<<grid, 256, SM1>>>(xh, w1, s1, t1,
                                              nullptr, nullptr, h1h);
    mma_conv_k<128, 1, 9><<<grid, 256, SM1>>>(h1h, w2, s2, t2,
                                              xt, nullptr, h2h);
    mma_conv_k<64, 2, 9><<<grid, 256, SMO>>>(h2h, wo, soff, toff,
                                             nullptr, offb_, nullptr);
    mma_deform_k<<<grid, 256, SMDEF>>>(h2h, offb_, wd, s3, t3, h3h);
    mma_conv_k<128, 4, 1><<<grid, 256, SMC>>>(h3h, wc, s4, t4,
                                              x, out, nullptr);
}